// round 4
// baseline (speedup 1.0000x reference)
#include <cuda_runtime.h>
#include <stdint.h>
#include <math.h>

#define NPOS 512          // positions per block
#define THREADS 128       // 4 positions per thread
#define CH 84
#define L_SEQ 8192
#define B_SEQ 16

// smem layout (float offsets)
#define AB_OFF 0          // 64 dims * 16 states * 2 (A,B)  = 2048
#define SB_OFF 2048       // class emit, [s][q] 16*16       = 256
#define K_OFF  2304       // 16
#define NB_OFF 2320       // 516 float4 nuc halo            = 2064
#define XS_OFF 4384       // 512 * 84 tile                  = 43008
#define SMEM_FLOATS 47392
#define SMEM_BYTES (SMEM_FLOATS * 4)

typedef unsigned long long ull;

__device__ __forceinline__ ull fma2(ull a, ull b, ull c) {
    ull d;
    asm("fma.rn.f32x2 %0, %1, %2, %3;" : "=l"(d) : "l"(a), "l"(b), "l"(c));
    return d;
}
__device__ __forceinline__ ull pk2(float lo, float hi) {
    ull d;
    asm("mov.b64 %0, {%1, %2};" : "=l"(d) : "f"(lo), "f"(hi));
    return d;
}
__device__ __forceinline__ void upk2(float& lo, float& hi, ull v) {
    asm("mov.b64 {%0, %1}, %2;" : "=f"(lo), "=f"(hi) : "l"(v));
}

__device__ __forceinline__ void cp_async16(unsigned int saddr, const void* gaddr) {
    asm volatile("cp.async.cg.shared.global [%0], [%1], 16;" :: "r"(saddr), "l"(gaddr));
}

// codon factor for one position; nbp points at nb entry for (global pos - 2)
__device__ __forceinline__ void codon_full(const float4* nbp, float* fullv) {
    float4 m2 = nbp[0], m1 = nbp[1], c0 = nbp[2], q1 = nbp[3], q2 = nbp[4];
    float S_c0 = c0.x + c0.y + c0.z + c0.w;
    float S_q1 = q1.x + q1.y + q1.z + q1.w;
    float S_q2 = q2.x + q2.y + q2.z + q2.w;
    float S_m1 = m1.x + m1.y + m1.z + m1.w;
    float S_m2 = m2.x + m2.y + m2.z + m2.w;
    float L_any   = S_c0 * S_q1 * S_q2 * (1.f / 64.f);
    float L_start = c0.x * q1.w * q2.z;           // ATG
    float L_ib    = 0.25f * S_c0 * q1.z * q2.w;   // NGT
    float Pall = S_m2 * S_m1 * S_c0;
    float tAA = m1.x * c0.x, tAG = m1.x * c0.z, tGA = m1.z * c0.x;
    float R_ns   = (Pall - m2.w * (tAA + tAG + tGA)) * (1.f / 61.f);
    float R_any  = Pall * (1.f / 64.f);
    float R_iep  = m2.x * m1.z * 0.25f * S_c0;    // AGN
    float R_stop = m2.w * (0.34f * tAA + 0.33f * tAG + 0.33f * tGA);
    fullv[0] = 1.f; fullv[1] = 1.f; fullv[2] = 1.f;
    fullv[3] = 1.f; fullv[4] = 1.f; fullv[5] = 1.f;
    fullv[6]  = L_any * R_ns;
    fullv[7]  = L_start * R_any;
    fullv[8]  = L_ib * R_any;
    fullv[9]  = L_ib * R_ns;
    fullv[10] = L_ib * R_any;
    fullv[11] = L_any * R_iep;
    fullv[12] = L_any * R_iep;
    fullv[13] = L_any * R_iep;
    fullv[14] = L_any * R_stop;
}

__global__ void __launch_bounds__(THREADS)
emit_kernel(const float* __restrict__ inputs,
            const float* __restrict__ eh,
            const float* __restrict__ ek,
            const float* __restrict__ eek,
            float* __restrict__ out) {
    extern __shared__ float sm[];
    const int tid = threadIdx.x;
    const int b  = blockIdx.x >> 4;
    const int p0 = (blockIdx.x & 15) << 9;

    // ---------------- phase 1: async tile load + inline prep ----------------
    const float4* in4 = (const float4*)(inputs + (size_t)(b * L_SEQ + p0) * CH);
    {
        unsigned int sbase = (unsigned int)__cvta_generic_to_shared(sm + XS_OFF);
#pragma unroll 4
        for (int i = tid; i < NPOS * CH / 4; i += THREADS)
            cp_async16(sbase + i * 16, in4 + i);
        asm volatile("cp.async.commit_group;");
    }

    const float kscale = (float)(1.4426950408889634 / 100.0); // log2(e)/TEMP
    const float basec  = (float)log(expm1(sqrt(0.05)));
    const float cconst = (float)(0.5 * 64.0 * log(2.0 * M_PI));

    // softmax rows of emission kernel -> SB[s][q]
    if (tid < 15) {
        int q = tid;
        float m = -1e30f;
        for (int s = 0; s < 15; s++) m = fmaxf(m, ek[q * 15 + s]);
        float e[15]; float sum = 0.f;
        for (int s = 0; s < 15; s++) { e[s] = expf(ek[q * 15 + s] - m); sum += e[s]; }
        float inv = 1.f / sum;
        for (int s = 0; s < 15; s++) sm[SB_OFF + s * 16 + q] = e[s] * inv;
    }
    if (tid == 15) {
        for (int s = 0; s < 16; s++) sm[SB_OFF + s * 16 + 15] = 0.f;
    }
    // MVN coefficients: thread t = s*8+g handles dims 8g..8g+7 of state s
    if (tid < 120) {
        int s = tid >> 3, g = tid & 7;
        float Cp = 0.f, ldp = 0.f;
        for (int k = 0; k < 8; k++) {
            int d = g * 8 + k;
            float mu = eek[s * 128 + d];
            float v  = eek[s * 128 + 64 + d] + basec;
            float sp = (v > 20.f) ? v : log1pf(expf(v));
            float is2 = 1.f / (sp * sp);
            sm[AB_OFF + d * 32 + s * 2 + 0] = -0.5f * is2 * kscale;
            sm[AB_OFF + d * 32 + s * 2 + 1] = mu * is2 * kscale;
            Cp  = fmaf(mu * mu, is2, Cp);
            ldp += logf(sp);
        }
        sm[NB_OFF + tid * 2 + 0] = Cp;   // scratch (NB region, rebuilt later)
        sm[NB_OFF + tid * 2 + 1] = ldp;
    } else if (tid >= 120 && tid < 128) {
        int g = tid - 120;
        for (int k = 0; k < 8; k++) {
            int d = g * 8 + k;
            sm[AB_OFF + d * 32 + 30] = 0.f;
            sm[AB_OFF + d * 32 + 31] = 0.f;
        }
    }
    __syncthreads();
    if (tid < 15) {
        float C = 0.f, ld = 0.f;
        for (int g = 0; g < 8; g++) {
            C  += sm[NB_OFF + (tid * 8 + g) * 2 + 0];
            ld += sm[NB_OFF + (tid * 8 + g) * 2 + 1];
        }
        sm[K_OFF + tid] = (-0.5f * C - ld - cconst) * kscale;
    } else if (tid == 15) {
        sm[K_OFF + 15] = 0.f;
    }
    asm volatile("cp.async.wait_group 0;");
    __syncthreads();

    // ---------------- phase 2: nucleotide halo buffer ----------------
    float4* nb = (float4*)(sm + NB_OFF);
    for (int i = tid; i < NPOS + 4; i += THREADS) {
        int gl = p0 + i - 2;
        float4 nv;
        if (gl >= 0 && gl < L_SEQ) {
            int li = gl - p0;
            const float* nr;
            if (li >= 0 && li < NPOS) nr = sm + XS_OFF + li * CH + 79;
            else                      nr = inputs + (size_t)(b * L_SEQ + gl) * CH + 79;
            float n4 = nr[4];
            nv = make_float4(fmaf(0.25f, n4, nr[0]), fmaf(0.25f, n4, nr[1]),
                             fmaf(0.25f, n4, nr[2]), fmaf(0.25f, n4, nr[3]));
        } else {
            nv = make_float4(0.25f, 0.25f, 0.25f, 0.25f);
        }
        nb[i] = nv;
    }
    __syncthreads();

    float* row0 = sm + XS_OFF + tid * CH;
    float* row1 = row0 + 128 * CH;
    float* row2 = row0 + 256 * CH;
    float* row3 = row0 + 384 * CH;

    // ====== phase A: class matvec + codon + hints -> staged into rows ======
    {
        // preload class channels (0..14) of all 4 positions
        float cls0[16], cls1[16], cls2[16], cls3[16];
#pragma unroll
        for (int j = 0; j < 4; j++) {
            *(float4*)(cls0 + 4 * j) = *(const float4*)(row0 + 4 * j);
            *(float4*)(cls1 + 4 * j) = *(const float4*)(row1 + 4 * j);
            *(float4*)(cls2 + 4 * j) = *(const float4*)(row2 + 4 * j);
            *(float4*)(cls3 + 4 * j) = *(const float4*)(row3 + 4 * j);
        }
        ull c0a[8], c1a[8], c2a[8], c3a[8];
#pragma unroll
        for (int h = 0; h < 8; h++) { c0a[h] = 0; c1a[h] = 0; c2a[h] = 0; c3a[h] = 0; }
#pragma unroll 3
        for (int s = 0; s < 15; s++) {
            const ulonglong2* br = (const ulonglong2*)(sm + SB_OFF + s * 16);
            ulonglong2 b01 = br[0], b23 = br[1], b45 = br[2], b67 = br[3];
            ull p0r = pk2(cls0[s], cls0[s]);
            ull p1r = pk2(cls1[s], cls1[s]);
            ull p2r = pk2(cls2[s], cls2[s]);
            ull p3r = pk2(cls3[s], cls3[s]);
            c0a[0]=fma2(b01.x,p0r,c0a[0]); c0a[1]=fma2(b01.y,p0r,c0a[1]);
            c0a[2]=fma2(b23.x,p0r,c0a[2]); c0a[3]=fma2(b23.y,p0r,c0a[3]);
            c0a[4]=fma2(b45.x,p0r,c0a[4]); c0a[5]=fma2(b45.y,p0r,c0a[5]);
            c0a[6]=fma2(b67.x,p0r,c0a[6]); c0a[7]=fma2(b67.y,p0r,c0a[7]);
            c1a[0]=fma2(b01.x,p1r,c1a[0]); c1a[1]=fma2(b01.y,p1r,c1a[1]);
            c1a[2]=fma2(b23.x,p1r,c1a[2]); c1a[3]=fma2(b23.y,p1r,c1a[3]);
            c1a[4]=fma2(b45.x,p1r,c1a[4]); c1a[5]=fma2(b45.y,p1r,c1a[5]);
            c1a[6]=fma2(b67.x,p1r,c1a[6]); c1a[7]=fma2(b67.y,p1r,c1a[7]);
            c2a[0]=fma2(b01.x,p2r,c2a[0]); c2a[1]=fma2(b01.y,p2r,c2a[1]);
            c2a[2]=fma2(b23.x,p2r,c2a[2]); c2a[3]=fma2(b23.y,p2r,c2a[3]);
            c2a[4]=fma2(b45.x,p2r,c2a[4]); c2a[5]=fma2(b45.y,p2r,c2a[5]);
            c2a[6]=fma2(b67.x,p2r,c2a[6]); c2a[7]=fma2(b67.y,p2r,c2a[7]);
            c3a[0]=fma2(b01.x,p3r,c3a[0]); c3a[1]=fma2(b01.y,p3r,c3a[1]);
            c3a[2]=fma2(b23.x,p3r,c3a[2]); c3a[3]=fma2(b23.y,p3r,c3a[3]);
            c3a[4]=fma2(b45.x,p3r,c3a[4]); c3a[5]=fma2(b45.y,p3r,c3a[5]);
            c3a[6]=fma2(b67.x,p3r,c3a[6]); c3a[7]=fma2(b67.y,p3r,c3a[7]);
        }
        float ca0[16], ca1[16], ca2[16], ca3[16];
#pragma unroll
        for (int h = 0; h < 8; h++) {
            upk2(ca0[2*h], ca0[2*h+1], c0a[h]);
            upk2(ca1[2*h], ca1[2*h+1], c1a[h]);
            upk2(ca2[2*h], ca2[2*h+1], c2a[h]);
            upk2(ca3[2*h], ca3[2*h+1], c3a[h]);
        }

        float* rows[4] = {row0, row1, row2, row3};
        float* cas[4]  = {ca0, ca1, ca2, ca3};
#pragma unroll
        for (int k = 0; k < 4; k++) {
            float fullv[15];
            codon_full(nb + tid + 128 * k, fullv);
            const int gl = p0 + tid + 128 * k;
            const float* hp = nullptr;
            if (gl == 0)              hp = eh + b * 30;
            else if (gl == L_SEQ - 1) hp = eh + b * 30 + 15;
            float* wr = rows[k];
#pragma unroll
            for (int q = 0; q < 15; q++) {
                float o = cas[k][q] * fullv[q];
                if (hp) o *= hp[q];
                wr[q] = o;   // stage into class channels (dead after this phase)
            }
        }
    }

    // ====== phase B: MVN exponents for 4 positions, 15 states ======
    ull a0[15], a1[15], a2[15], a3[15];
#pragma unroll
    for (int q = 0; q < 15; q++) {
        float Kq = sm[K_OFF + q];
        ull init = pk2(Kq, 0.f);
        a0[q] = init; a1[q] = init; a2[q] = init; a3[q] = init;
    }

#define PROC4(d, x0, x1, x2, x3)                                        \
    {                                                                   \
        ull xa0 = pk2((x0) * (x0), (x0));                               \
        ull xa1 = pk2((x1) * (x1), (x1));                               \
        ull xa2 = pk2((x2) * (x2), (x2));                               \
        ull xa3 = pk2((x3) * (x3), (x3));                               \
        const ulonglong2* cdim =                                        \
            (const ulonglong2*)(sm + AB_OFF + (d) * 32);                \
        _Pragma("unroll")                                               \
        for (int h = 0; h < 7; h++) {                                   \
            ulonglong2 cv = cdim[h];                                    \
            a0[2*h]   = fma2(cv.x, xa0, a0[2*h]);                       \
            a0[2*h+1] = fma2(cv.y, xa0, a0[2*h+1]);                     \
            a1[2*h]   = fma2(cv.x, xa1, a1[2*h]);                       \
            a1[2*h+1] = fma2(cv.y, xa1, a1[2*h+1]);                     \
            a2[2*h]   = fma2(cv.x, xa2, a2[2*h]);                       \
            a2[2*h+1] = fma2(cv.y, xa2, a2[2*h+1]);                     \
            a3[2*h]   = fma2(cv.x, xa3, a3[2*h]);                       \
            a3[2*h+1] = fma2(cv.y, xa3, a3[2*h+1]);                     \
        }                                                               \
        ull cv14 = *(const ull*)(sm + AB_OFF + (d) * 32 + 28);          \
        a0[14] = fma2(cv14, xa0, a0[14]);                               \
        a1[14] = fma2(cv14, xa1, a1[14]);                               \
        a2[14] = fma2(cv14, xa2, a2[14]);                               \
        a3[14] = fma2(cv14, xa3, a3[14]);                               \
    }

    PROC4(0, row0[15], row1[15], row2[15], row3[15]);
#pragma unroll 1
    for (int j = 0; j < 15; j++) {        // dims 1..60 (channels 16..75)
        float4 v0 = *(const float4*)(row0 + 16 + 4 * j);
        float4 v1 = *(const float4*)(row1 + 16 + 4 * j);
        float4 v2 = *(const float4*)(row2 + 16 + 4 * j);
        float4 v3 = *(const float4*)(row3 + 16 + 4 * j);
        int d = 4 * j + 1;
        PROC4(d,     v0.x, v1.x, v2.x, v3.x);
        PROC4(d + 1, v0.y, v1.y, v2.y, v3.y);
        PROC4(d + 2, v0.z, v1.z, v2.z, v3.z);
        PROC4(d + 3, v0.w, v1.w, v2.w, v3.w);
    }
    {
        float4 v0 = *(const float4*)(row0 + 76);   // dims 61..63
        float4 v1 = *(const float4*)(row1 + 76);
        float4 v2 = *(const float4*)(row2 + 76);
        float4 v3 = *(const float4*)(row3 + 76);
        PROC4(61, v0.x, v1.x, v2.x, v3.x);
        PROC4(62, v0.y, v1.y, v2.y, v3.y);
        PROC4(63, v0.z, v1.z, v2.z, v3.z);
    }

    // final: multiply staged (class*codon*hint) by exp2(exponent), in place
#pragma unroll
    for (int q = 0; q < 15; q++) {
        float lo, hi;
        upk2(lo, hi, a0[q]); row0[q] *= exp2f(lo + hi);
        upk2(lo, hi, a1[q]); row1[q] *= exp2f(lo + hi);
        upk2(lo, hi, a2[q]); row2[q] *= exp2f(lo + hi);
        upk2(lo, hi, a3[q]); row3[q] *= exp2f(lo + hi);
    }
    __syncthreads();

    // coalesced flush
    float* og = out + (size_t)(b * L_SEQ + p0) * 15;
#pragma unroll 6
    for (int i = tid; i < NPOS * 15; i += THREADS) {
        int pos = i / 15;
        int q   = i - pos * 15;
        og[i] = sm[XS_OFF + pos * CH + q];
    }
}

extern "C" void kernel_launch(void* const* d_in, const int* in_sizes, int n_in,
                              void* d_out, int out_size) {
    const float *inp = nullptr, *eh = nullptr, *ek = nullptr, *eek = nullptr;
    for (int i = 0; i < n_in; i++) {
        switch (in_sizes[i]) {
            case 11010048: inp = (const float*)d_in[i]; break; // inputs
            case 480:      eh  = (const float*)d_in[i]; break; // end_hints
            case 225:      ek  = (const float*)d_in[i]; break; // emission_kernel
            case 1920:     eek = (const float*)d_in[i]; break; // embedding_emission_kernel
        }
    }
    float* out = (float*)d_out;

    cudaFuncSetAttribute(emit_kernel, cudaFuncAttributeMaxDynamicSharedMemorySize,
                         SMEM_BYTES);

    emit_kernel<<<(B_SEQ * L_SEQ) / NPOS, THREADS, SMEM_BYTES>>>(inp, eh, ek, eek, out);
}